// round 2
// baseline (speedup 1.0000x reference)
#include <cuda_runtime.h>

// Problem constants (fixed shapes from reference)
constexpr int Bb   = 8;
constexpr int Tt   = 12;
constexpr int Nn   = 1500;
constexpr int HID_ = 64;
constexpr int BN   = Bb * Nn;     // 12000
constexpr int SPB  = 32;          // sequences per LSTM block
constexpr int SPBP = 36;          // padded row (bank-conflict + 16B alignment)

#define DEVINL __device__ __forceinline__

// ---------------- scratch (device globals; no allocation allowed) ----------
__device__ __align__(16) float d_WhhT0[64 * 256];
__device__ __align__(16) float d_WihT1[64 * 256];
__device__ __align__(16) float d_WhhT1[64 * 256];
__device__ float d_b0[256], d_b1[256];
__device__ __align__(16) float d_g0WT[64 * 64], d_g1WT[64 * 64];
__device__ __align__(16) float d_h [BN * 64];   // LSTM out / GAT1 out (final hidden)
__device__ __align__(16) float d_h2[BN * 64];   // GAT0 out
__device__ __align__(16) float d_hp[BN * 64];   // per-layer projected features
__device__ float d_es[BN * 4], d_ed[BN * 4];

DEVINL float fsig(float z)  { return __fdividef(1.f, 1.f + __expf(-z)); }
DEVINL float ftanh(float z) { return __fdividef(2.f, 1.f + __expf(-2.f * z)) - 1.f; }

// ---------------- prep: transposes + fused biases ---------------------------
__global__ void prep_kernel(const float* __restrict__ Whh0,
                            const float* __restrict__ bih0, const float* __restrict__ bhh0,
                            const float* __restrict__ Wih1, const float* __restrict__ Whh1,
                            const float* __restrict__ bih1, const float* __restrict__ bhh1,
                            const float* __restrict__ g0W,  const float* __restrict__ g1W)
{
    int idx = blockIdx.x * blockDim.x + threadIdx.x;
    if (idx < 16384) {
        int r = idx >> 6, j = idx & 63;
        d_WhhT0[j * 256 + r] = Whh0[idx];
        d_WihT1[j * 256 + r] = Wih1[idx];
        d_WhhT1[j * 256 + r] = Whh1[idx];
    }
    if (idx < 256) {
        d_b0[idx] = bih0[idx] + bhh0[idx];
        d_b1[idx] = bih1[idx] + bhh1[idx];
    }
    if (idx < 4096) {
        int o = idx >> 6, k = idx & 63;
        d_g0WT[k * 64 + o] = g0W[idx];
        d_g1WT[k * 64 + o] = g1W[idx];
    }
}

// ---------------- 2-layer LSTM ----------------------------------------------
// block: 256 threads = (unit u in 0..63) x (seq-group sg in 0..3, 8 seqs each)
__global__ __launch_bounds__(256) void lstm_kernel(
    const float* __restrict__ x,      // (B,T,N)
    const float* __restrict__ Wih0)   // (256,1)
{
    __shared__ float xs[Tt][SPB];
    __shared__ __align__(16) float h0s[HID_][SPBP];
    __shared__ __align__(16) float h1s[HID_][SPBP];

    const int tid = threadIdx.x;
    const int u   = tid & 63;
    const int sg  = tid >> 6;
    const int sbase = sg * 8;
    const int bn0 = blockIdx.x * SPB;

    // load x tile (T x 32 seqs)
    for (int idx = tid; idx < Tt * SPB; idx += 256) {
        int tt = idx / SPB, s = idx % SPB;
        int bn = bn0 + s;
        int b = bn / Nn, n = bn % Nn;
        xs[tt][s] = x[(b * Tt + tt) * Nn + n];
    }
    // zero h state (including pads)
    for (int idx = tid; idx < HID_ * SPBP; idx += 256) {
        (&h0s[0][0])[idx] = 0.f;
        (&h1s[0][0])[idx] = 0.f;
    }

    float c0[8], c1[8];
#pragma unroll
    for (int s = 0; s < 8; ++s) { c0[s] = 0.f; c1[s] = 0.f; }

    // invariant per-thread weights/biases
    const float wi0_i = Wih0[u],       wi0_f = Wih0[64 + u];
    const float wi0_g = Wih0[128 + u], wi0_o = Wih0[192 + u];
    const float b0_i = d_b0[u], b0_f = d_b0[64 + u], b0_g = d_b0[128 + u], b0_o = d_b0[192 + u];
    const float b1_i = d_b1[u], b1_f = d_b1[64 + u], b1_g = d_b1[128 + u], b1_o = d_b1[192 + u];

    __syncthreads();

    float h1v[8];
    for (int t = 0; t < Tt; ++t) {
        // ---- layer 0 gates ----
        float ai[8], af[8], ag[8], ao[8];
#pragma unroll
        for (int s = 0; s < 8; ++s) {
            float xv = xs[t][sbase + s];
            ai[s] = fmaf(wi0_i, xv, b0_i);
            af[s] = fmaf(wi0_f, xv, b0_f);
            ag[s] = fmaf(wi0_g, xv, b0_g);
            ao[s] = fmaf(wi0_o, xv, b0_o);
        }
#pragma unroll 2
        for (int j = 0; j < HID_; ++j) {
            const float* wr = &d_WhhT0[j * 256 + u];
            float wi = wr[0], wf = wr[64], wg = wr[128], wo = wr[192];
            float4 ha = *(const float4*)&h0s[j][sbase];
            float4 hb = *(const float4*)&h0s[j][sbase + 4];
            float hv[8] = {ha.x, ha.y, ha.z, ha.w, hb.x, hb.y, hb.z, hb.w};
#pragma unroll
            for (int s = 0; s < 8; ++s) {
                ai[s] = fmaf(wi, hv[s], ai[s]);
                af[s] = fmaf(wf, hv[s], af[s]);
                ag[s] = fmaf(wg, hv[s], ag[s]);
                ao[s] = fmaf(wo, hv[s], ao[s]);
            }
        }
        float h0v[8];
#pragma unroll
        for (int s = 0; s < 8; ++s) {
            float ig = fsig(ai[s]), fg = fsig(af[s]);
            float gg = ftanh(ag[s]), og = fsig(ao[s]);
            c0[s] = fmaf(fg, c0[s], ig * gg);
            h0v[s] = og * ftanh(c0[s]);
        }
        __syncthreads();           // all reads of h0s(t-1) done
#pragma unroll
        for (int s = 0; s < 8; ++s) h0s[u][sbase + s] = h0v[s];
        __syncthreads();           // h0s(t) visible

        // ---- layer 1 gates ----
#pragma unroll
        for (int s = 0; s < 8; ++s) { ai[s] = b1_i; af[s] = b1_f; ag[s] = b1_g; ao[s] = b1_o; }
#pragma unroll 2
        for (int j = 0; j < HID_; ++j) {
            const float* wr = &d_WihT1[j * 256 + u];
            float wi = wr[0], wf = wr[64], wg = wr[128], wo = wr[192];
            float4 ha = *(const float4*)&h0s[j][sbase];
            float4 hb = *(const float4*)&h0s[j][sbase + 4];
            float hv[8] = {ha.x, ha.y, ha.z, ha.w, hb.x, hb.y, hb.z, hb.w};
#pragma unroll
            for (int s = 0; s < 8; ++s) {
                ai[s] = fmaf(wi, hv[s], ai[s]);
                af[s] = fmaf(wf, hv[s], af[s]);
                ag[s] = fmaf(wg, hv[s], ag[s]);
                ao[s] = fmaf(wo, hv[s], ao[s]);
            }
        }
#pragma unroll 2
        for (int j = 0; j < HID_; ++j) {
            const float* wr = &d_WhhT1[j * 256 + u];
            float wi = wr[0], wf = wr[64], wg = wr[128], wo = wr[192];
            float4 ha = *(const float4*)&h1s[j][sbase];
            float4 hb = *(const float4*)&h1s[j][sbase + 4];
            float hv[8] = {ha.x, ha.y, ha.z, ha.w, hb.x, hb.y, hb.z, hb.w};
#pragma unroll
            for (int s = 0; s < 8; ++s) {
                ai[s] = fmaf(wi, hv[s], ai[s]);
                af[s] = fmaf(wf, hv[s], af[s]);
                ag[s] = fmaf(wg, hv[s], ag[s]);
                ao[s] = fmaf(wo, hv[s], ao[s]);
            }
        }
#pragma unroll
        for (int s = 0; s < 8; ++s) {
            float ig = fsig(ai[s]), fg = fsig(af[s]);
            float gg = ftanh(ag[s]), og = fsig(ao[s]);
            c1[s] = fmaf(fg, c1[s], ig * gg);
            h1v[s] = og * ftanh(c1[s]);
        }
        __syncthreads();           // all reads of h1s(t-1) done
#pragma unroll
        for (int s = 0; s < 8; ++s) h1s[u][sbase + s] = h1v[s];
        __syncthreads();
    }

    // last-step top-layer hidden -> d_h
#pragma unroll
    for (int s = 0; s < 8; ++s)
        d_h[(bn0 + sbase + s) * 64 + u] = h1v[s];
}

// ---------------- GAT projection + attention coefficients -------------------
// block: 256 threads = 4 nodes x 64 outputs
template <int LAYER>
__global__ __launch_bounds__(256) void gat_proj_kernel(
    const float* __restrict__ asrc, const float* __restrict__ adst)
{
    const float* __restrict__ hin = (LAYER == 0) ? d_h : d_h2;
    const float* __restrict__ WT  = (LAYER == 0) ? d_g0WT : d_g1WT;

    const int t  = threadIdx.x;
    const int o  = t & 63;
    const int lo = t >> 6;
    const int bn = blockIdx.x * 4 + lo;

    __shared__ float hs[4][64];
    hs[lo][o] = hin[bn * 64 + o];
    __syncthreads();

    float acc = 0.f;
#pragma unroll
    for (int k = 0; k < 64; ++k)
        acc = fmaf(hs[lo][k], WT[k * 64 + o], acc);

    d_hp[bn * 64 + o] = acc;

    float vs = acc * asrc[o];
    float vd = acc * adst[o];
#pragma unroll
    for (int off = 8; off > 0; off >>= 1) {
        vs += __shfl_down_sync(0xffffffffu, vs, off, 16);
        vd += __shfl_down_sync(0xffffffffu, vd, off, 16);
    }
    if ((o & 15) == 0) {
        int hh = o >> 4;
        d_es[bn * 4 + hh] = vs;
        d_ed[bn * 4 + hh] = vd;
    }
}

// ---------------- GAT masked softmax attention + aggregate + ReLU -----------
// block: 128 threads = 32 rows x 4 heads; grid (ceil(N/32), B)
template <int LAYER>
__global__ __launch_bounds__(128) void gat_attn_kernel(const int* __restrict__ adj)
{
    float* __restrict__ hout = (LAYER == 0) ? d_h2 : d_h;

    constexpr int TI = 32, JC = 64;
    const int b  = blockIdx.y;
    const int i0 = blockIdx.x * TI;
    const int t  = threadIdx.x;
    const int h  = t & 3;
    const int il = t >> 2;
    const int i  = i0 + il;
    const bool ivalid = (i < Nn);

    __shared__ __align__(16) float hps[JC][64];   // 16 KB
    __shared__ float eds[JC][4];
    __shared__ int   adjs[TI][JC + 1];

    float acc[16];
#pragma unroll
    for (int d = 0; d < 16; ++d) acc[d] = 0.f;
    float ssum = 0.f;
    const float es = ivalid ? d_es[(b * Nn + i) * 4 + h] : 0.f;

    for (int j0 = 0; j0 < Nn; j0 += JC) {
        __syncthreads();
        // hp chunk: 64 nodes x 64 feats as float4
        for (int idx = t; idx < JC * 16; idx += 128) {
            int jj = idx >> 4, k4 = idx & 15;
            int j = j0 + jj;
            float4 v = make_float4(0.f, 0.f, 0.f, 0.f);
            if (j < Nn) v = ((const float4*)d_hp)[(b * Nn + j) * 16 + k4];
            ((float4*)hps)[idx] = v;
        }
        for (int idx = t; idx < JC * 4; idx += 128) {
            int jj = idx >> 2, hh = idx & 3;
            int j = j0 + jj;
            eds[jj][hh] = (j < Nn) ? d_ed[(b * Nn + j) * 4 + hh] : 0.f;
        }
        for (int idx = t; idx < TI * JC; idx += 128) {
            int ril = idx / JC, jj = idx % JC;
            int ii = i0 + ril, j = j0 + jj;
            adjs[ril][jj] = (ii < Nn && j < Nn) ? adj[ii * Nn + j] : 0;
        }
        __syncthreads();

        if (ivalid) {
            const int jmax = min(JC, Nn - j0);
            for (int jj = 0; jj < jmax; ++jj) {
                if (adjs[il][jj] > 0) {
                    float e = es + eds[jj][h];
                    e = fmaxf(e, 0.2f * e);          // LeakyReLU(0.2)
                    float p = __expf(e);             // no max-shift needed: |e| is O(1)
                    ssum += p;
                    const float* hpj = &hps[jj][h * 16];
#pragma unroll
                    for (int d = 0; d < 16; ++d)
                        acc[d] = fmaf(p, hpj[d], acc[d]);
                }
            }
        }
    }

    if (ivalid) {
        float inv = (ssum > 0.f) ? __fdividef(1.f, ssum) : 0.f;
        float* dst = &hout[(b * Nn + i) * 64 + h * 16];
#pragma unroll
        for (int d = 0; d < 16; ++d) {
            float v = acc[d] * inv;
            dst[d] = (v > 0.f) ? v : 0.f;            // ReLU
        }
    }
}

// ---------------- output head: (B,N,64) @ (3,64)^T -> (B,3,N) ---------------
__global__ __launch_bounds__(256) void out_kernel(
    const float* __restrict__ outW, const float* __restrict__ outb,
    float* __restrict__ out)
{
    int gw   = (blockIdx.x * blockDim.x + threadIdx.x) >> 5;  // warp id == bn
    int lane = threadIdx.x & 31;
    if (gw >= BN) return;
    float ha = d_h[gw * 64 + lane];
    float hb = d_h[gw * 64 + 32 + lane];
    int b = gw / Nn, n = gw % Nn;
#pragma unroll
    for (int o = 0; o < 3; ++o) {
        float p = fmaf(ha, outW[o * 64 + lane], hb * outW[o * 64 + 32 + lane]);
#pragma unroll
        for (int off = 16; off > 0; off >>= 1)
            p += __shfl_down_sync(0xffffffffu, p, off);
        if (lane == 0)
            out[b * 3 * Nn + o * Nn + n] = p + outb[o];
    }
}

// ---------------- launch ----------------------------------------------------
extern "C" void kernel_launch(void* const* d_in, const int* in_sizes, int n_in,
                              void* d_out, int out_size)
{
    const float* x     = (const float*)d_in[0];
    const int*   adj   = (const int*)  d_in[1];
    const float* Wih0  = (const float*)d_in[2];
    const float* Whh0  = (const float*)d_in[3];
    const float* bih0  = (const float*)d_in[4];
    const float* bhh0  = (const float*)d_in[5];
    const float* Wih1  = (const float*)d_in[6];
    const float* Whh1  = (const float*)d_in[7];
    const float* bih1  = (const float*)d_in[8];
    const float* bhh1  = (const float*)d_in[9];
    const float* g0W   = (const float*)d_in[10];
    const float* g0as  = (const float*)d_in[11];
    const float* g0ad  = (const float*)d_in[12];
    const float* g1W   = (const float*)d_in[13];
    const float* g1as  = (const float*)d_in[14];
    const float* g1ad  = (const float*)d_in[15];
    const float* outW  = (const float*)d_in[16];
    const float* outb  = (const float*)d_in[17];
    float* out = (float*)d_out;

    prep_kernel<<<64, 256>>>(Whh0, bih0, bhh0, Wih1, Whh1, bih1, bhh1, g0W, g1W);
    lstm_kernel<<<BN / SPB, 256>>>(x, Wih0);

    gat_proj_kernel<0><<<BN / 4, 256>>>(g0as, g0ad);
    gat_attn_kernel<0><<<dim3((Nn + 31) / 32, Bb), 128>>>(adj);

    gat_proj_kernel<1><<<BN / 4, 256>>>(g1as, g1ad);
    gat_attn_kernel<1><<<dim3((Nn + 31) / 32, Bb), 128>>>(adj);

    out_kernel<<<(BN * 32 + 255) / 256, 256>>>(outW, outb, out);
}

// round 4
// speedup vs baseline: 1.6694x; 1.6694x over previous
#include <cuda_runtime.h>

// Problem constants (fixed shapes from reference)
constexpr int Bb   = 8;
constexpr int Tt   = 12;
constexpr int Nn   = 1500;
constexpr int HID_ = 64;
constexpr int BN   = Bb * Nn;     // 12000
constexpr int SPB  = 32;          // sequences per LSTM block
constexpr int SPBP = 36;          // padded row
constexpr int NW   = 47;          // ceil(1500/32) adjacency bitmask words per row
constexpr int JSPLIT0 = 768;      // z=0 covers j in [0,768), z=1 covers [768,1500)

#define DEVINL __device__ __forceinline__

// ---------------- scratch (device globals; no allocation allowed) ----------
__device__ __align__(16) float d_Wp0[64 * 256];    // [j][u][gate] packed, layer0 Whh
__device__ __align__(16) float d_Wp1i[64 * 256];   // layer1 Wih packed
__device__ __align__(16) float d_Wp1h[64 * 256];   // layer1 Whh packed
__device__ float d_b0[256], d_b1[256];
__device__ __align__(16) float d_g0WT[64 * 64], d_g1WT[64 * 64];
__device__ __align__(16) float d_h [BN * 64];      // LSTM out / GAT1 out
__device__ __align__(16) float d_h2[BN * 64];      // GAT0 out
__device__ __align__(16) float d_hp[BN * 64];      // projected features (per layer)
__device__ __align__(16) float4 d_esv[BN * 4];     // (exp(es), exp(0.2es), es, 0)
__device__ __align__(16) float4 d_edv[BN * 4];     // (exp(ed), exp(0.2ed), ed, 0)
__device__ unsigned d_adjb[Nn * NW];               // bitpacked adjacency
__device__ __align__(16) float d_pacc0[BN * 64], d_pacc1[BN * 64];
__device__ float d_pss0[BN * 4], d_pss1[BN * 4];

DEVINL float fsig(float z)  { return __fdividef(1.f, 1.f + __expf(-z)); }
DEVINL float ftanh(float z) { return __fdividef(2.f, 1.f + __expf(-2.f * z)) - 1.f; }

// ---------------- prep: packed transposes + fused biases + adj bitpack ------
__global__ void prep_kernel(const float* __restrict__ adj_,
                            const float* __restrict__ Whh0,
                            const float* __restrict__ bih0, const float* __restrict__ bhh0,
                            const float* __restrict__ Wih1, const float* __restrict__ Whh1,
                            const float* __restrict__ bih1, const float* __restrict__ bhh1,
                            const float* __restrict__ g0W,  const float* __restrict__ g1W)
{
    const int* __restrict__ adj = (const int*)adj_;
    int idx = blockIdx.x * blockDim.x + threadIdx.x;
    if (idx < 16384) {
        int r = idx >> 6, j = idx & 63;
        int g = r >> 6, u = r & 63;
        int p = j * 256 + u * 4 + g;
        d_Wp0 [p] = Whh0[idx];
        d_Wp1i[p] = Wih1[idx];
        d_Wp1h[p] = Whh1[idx];
    }
    if (idx < 256) {
        d_b0[idx] = bih0[idx] + bhh0[idx];
        d_b1[idx] = bih1[idx] + bhh1[idx];
    }
    if (idx < 4096) {
        int o = idx >> 6, k = idx & 63;
        d_g0WT[k * 64 + o] = g0W[idx];
        d_g1WT[k * 64 + o] = g1W[idx];
    }
    if (idx < Nn * NW) {
        int i = idx / NW, w = idx % NW;
        unsigned m = 0;
        int jb = w * 32;
#pragma unroll 8
        for (int b = 0; b < 32; ++b) {
            int j = jb + b;
            if (j < Nn && adj[i * Nn + j] > 0) m |= (1u << b);
        }
        d_adjb[idx] = m;
    }
}

// ---------------- 2-layer LSTM ----------------------------------------------
__global__ __launch_bounds__(256) void lstm_kernel(
    const float* __restrict__ x, const float* __restrict__ Wih0)
{
    __shared__ float xs[Tt][SPB];
    __shared__ __align__(16) float h0s[HID_][SPBP];
    __shared__ __align__(16) float h1s[HID_][SPBP];

    const int tid = threadIdx.x;
    const int u   = tid & 63;
    const int sg  = tid >> 6;
    const int sbase = sg * 8;
    const int bn0 = blockIdx.x * SPB;

    for (int idx = tid; idx < Tt * SPB; idx += 256) {
        int tt = idx / SPB, s = idx % SPB;
        int bn = bn0 + s;
        int b = bn / Nn, n = bn % Nn;
        xs[tt][s] = x[(b * Tt + tt) * Nn + n];
    }
    for (int idx = tid; idx < HID_ * SPBP; idx += 256) {
        (&h0s[0][0])[idx] = 0.f;
        (&h1s[0][0])[idx] = 0.f;
    }

    float c0[8], c1[8];
#pragma unroll
    for (int s = 0; s < 8; ++s) { c0[s] = 0.f; c1[s] = 0.f; }

    const float wi0_i = Wih0[u],       wi0_f = Wih0[64 + u];
    const float wi0_g = Wih0[128 + u], wi0_o = Wih0[192 + u];
    const float b0_i = d_b0[u], b0_f = d_b0[64 + u], b0_g = d_b0[128 + u], b0_o = d_b0[192 + u];
    const float b1_i = d_b1[u], b1_f = d_b1[64 + u], b1_g = d_b1[128 + u], b1_o = d_b1[192 + u];

    const float4* __restrict__ Wp0  = (const float4*)&d_Wp0 [u * 4];
    const float4* __restrict__ Wp1i = (const float4*)&d_Wp1i[u * 4];
    const float4* __restrict__ Wp1h = (const float4*)&d_Wp1h[u * 4];

    __syncthreads();

    float h1v[8];
    for (int t = 0; t < Tt; ++t) {
        // ---- layer 0 gates ----
        float ai[8], af[8], ag[8], ao[8];
#pragma unroll
        for (int s = 0; s < 8; ++s) {
            float xv = xs[t][sbase + s];
            ai[s] = fmaf(wi0_i, xv, b0_i);
            af[s] = fmaf(wi0_f, xv, b0_f);
            ag[s] = fmaf(wi0_g, xv, b0_g);
            ao[s] = fmaf(wi0_o, xv, b0_o);
        }
#pragma unroll 4
        for (int j = 0; j < HID_; ++j) {
            float4 w = Wp0[j * 64];
            float4 ha = *(const float4*)&h0s[j][sbase];
            float4 hb = *(const float4*)&h0s[j][sbase + 4];
            float hv[8] = {ha.x, ha.y, ha.z, ha.w, hb.x, hb.y, hb.z, hb.w};
#pragma unroll
            for (int s = 0; s < 8; ++s) {
                ai[s] = fmaf(w.x, hv[s], ai[s]);
                af[s] = fmaf(w.y, hv[s], af[s]);
                ag[s] = fmaf(w.z, hv[s], ag[s]);
                ao[s] = fmaf(w.w, hv[s], ao[s]);
            }
        }
        float h0v[8];
#pragma unroll
        for (int s = 0; s < 8; ++s) {
            float ig = fsig(ai[s]), fg = fsig(af[s]);
            float gg = ftanh(ag[s]), og = fsig(ao[s]);
            c0[s] = fmaf(fg, c0[s], ig * gg);
            h0v[s] = og * ftanh(c0[s]);
        }
        __syncthreads();
#pragma unroll
        for (int s = 0; s < 8; ++s) h0s[u][sbase + s] = h0v[s];
        __syncthreads();

        // ---- layer 1 gates ----
#pragma unroll
        for (int s = 0; s < 8; ++s) { ai[s] = b1_i; af[s] = b1_f; ag[s] = b1_g; ao[s] = b1_o; }
#pragma unroll 4
        for (int j = 0; j < HID_; ++j) {
            float4 w = Wp1i[j * 64];
            float4 ha = *(const float4*)&h0s[j][sbase];
            float4 hb = *(const float4*)&h0s[j][sbase + 4];
            float hv[8] = {ha.x, ha.y, ha.z, ha.w, hb.x, hb.y, hb.z, hb.w};
#pragma unroll
            for (int s = 0; s < 8; ++s) {
                ai[s] = fmaf(w.x, hv[s], ai[s]);
                af[s] = fmaf(w.y, hv[s], af[s]);
                ag[s] = fmaf(w.z, hv[s], ag[s]);
                ao[s] = fmaf(w.w, hv[s], ao[s]);
            }
        }
#pragma unroll 4
        for (int j = 0; j < HID_; ++j) {
            float4 w = Wp1h[j * 64];
            float4 ha = *(const float4*)&h1s[j][sbase];
            float4 hb = *(const float4*)&h1s[j][sbase + 4];
            float hv[8] = {ha.x, ha.y, ha.z, ha.w, hb.x, hb.y, hb.z, hb.w};
#pragma unroll
            for (int s = 0; s < 8; ++s) {
                ai[s] = fmaf(w.x, hv[s], ai[s]);
                af[s] = fmaf(w.y, hv[s], af[s]);
                ag[s] = fmaf(w.z, hv[s], ag[s]);
                ao[s] = fmaf(w.w, hv[s], ao[s]);
            }
        }
#pragma unroll
        for (int s = 0; s < 8; ++s) {
            float ig = fsig(ai[s]), fg = fsig(af[s]);
            float gg = ftanh(ag[s]), og = fsig(ao[s]);
            c1[s] = fmaf(fg, c1[s], ig * gg);
            h1v[s] = og * ftanh(c1[s]);
        }
        __syncthreads();
#pragma unroll
        for (int s = 0; s < 8; ++s) h1s[u][sbase + s] = h1v[s];
        __syncthreads();
    }

#pragma unroll
    for (int s = 0; s < 8; ++s)
        d_h[(bn0 + sbase + s) * 64 + u] = h1v[s];
}

// ---------------- GAT projection + factorized attention exponentials -------
template <int LAYER>
__global__ __launch_bounds__(256) void gat_proj_kernel(
    const float* __restrict__ asrc, const float* __restrict__ adst)
{
    const float* __restrict__ hin = (LAYER == 0) ? d_h : d_h2;
    const float* __restrict__ WT  = (LAYER == 0) ? d_g0WT : d_g1WT;

    const int t  = threadIdx.x;
    const int o  = t & 63;
    const int lo = t >> 6;
    const int bn = blockIdx.x * 4 + lo;

    __shared__ float hs[4][64];
    hs[lo][o] = hin[bn * 64 + o];
    __syncthreads();

    float acc = 0.f;
#pragma unroll
    for (int k = 0; k < 64; ++k)
        acc = fmaf(hs[lo][k], WT[k * 64 + o], acc);

    d_hp[bn * 64 + o] = acc;

    float vs = acc * asrc[o];
    float vd = acc * adst[o];
#pragma unroll
    for (int off = 8; off > 0; off >>= 1) {
        vs += __shfl_down_sync(0xffffffffu, vs, off, 16);
        vd += __shfl_down_sync(0xffffffffu, vd, off, 16);
    }
    if ((o & 15) == 0) {
        int hh = o >> 4;
        d_esv[bn * 4 + hh] = make_float4(__expf(vs), __expf(0.2f * vs), vs, 0.f);
        d_edv[bn * 4 + hh] = make_float4(__expf(vd), __expf(0.2f * vd), vd, 0.f);
    }
}

// ---------------- GAT attention aggregate (j-split, partial results) --------
// block: 128 threads = 32 rslots x 4 heads; each thread owns 2 rows
// grid: (ceil(N/64), B, 2)
__global__ __launch_bounds__(128) void gat_attn_kernel()
{
    constexpr int JC = 64;
    const int b  = blockIdx.y;
    const int z  = blockIdx.z;
    const int i0 = blockIdx.x * 64;
    const int t  = threadIdx.x;
    const int h  = t & 3;
    const int rs = t >> 2;

    float* __restrict__ pacc = z ? d_pacc1 : d_pacc0;
    float* __restrict__ pss  = z ? d_pss1  : d_pss0;

    __shared__ __align__(16) float4 hps4[JC][16];   // 16 KB  [jj][k4]
    __shared__ __align__(16) float4 edvs[JC][4];    // 4 KB   [jj][h]
    __shared__ unsigned adjw[64][2];                // 512 B

    float acc[2][16];
#pragma unroll
    for (int r = 0; r < 2; ++r)
#pragma unroll
        for (int d = 0; d < 16; ++d) acc[r][d] = 0.f;
    float ssum[2] = {0.f, 0.f};

    int   irow[2];
    float esA[2], esB[2], esr[2];
#pragma unroll
    for (int r = 0; r < 2; ++r) {
        irow[r] = i0 + rs + 32 * r;
        float4 ev = make_float4(0.f, 0.f, 0.f, 0.f);
        if (irow[r] < Nn) ev = d_esv[(b * Nn + irow[r]) * 4 + h];
        esA[r] = ev.x; esB[r] = ev.y; esr[r] = ev.z;
    }

    const int jbeg = z ? JSPLIT0 : 0;
    const int jend = z ? Nn : JSPLIT0;

    for (int j0 = jbeg; j0 < jend; j0 += JC) {
        __syncthreads();
        // hp chunk: JC nodes x 64 feats
        for (int idx = t; idx < JC * 16; idx += 128) {
            int jj = idx >> 4, k4 = idx & 15;
            int j = j0 + jj;
            float4 v = make_float4(0.f, 0.f, 0.f, 0.f);
            if (j < Nn) v = ((const float4*)d_hp)[(b * Nn + j) * 16 + k4];
            hps4[jj][k4] = v;
        }
        for (int idx = t; idx < JC * 4; idx += 128) {
            int jj = idx >> 2, hh = idx & 3;
            int j = j0 + jj;
            float4 v = make_float4(0.f, 0.f, 0.f, 0.f);
            if (j < Nn) v = d_edv[(b * Nn + j) * 4 + hh];
            edvs[jj][hh] = v;
        }
        {
            int i = i0 + t & 0x7fffffff; // t in 0..127, but rows only 64 -> use t<64 pattern
        }
        if (t < 64) {
            int i = i0 + t;
            int w0 = j0 >> 5;
#pragma unroll
            for (int w = 0; w < 2; ++w) {
                unsigned m = 0;
                if (i < Nn && (w0 + w) < NW) m = d_adjb[i * NW + w0 + w];
                adjw[t][w] = m;
            }
        }
        __syncthreads();

#pragma unroll
        for (int w = 0; w < 2; ++w) {
            unsigned m0 = adjw[rs][w];
            unsigned m1 = adjw[rs + 32][w];
            const int jjb = w * 32;
#pragma unroll 4
            for (int bp = 0; bp < 32; ++bp) {
                const int jj = jjb + bp;
                float4 ed = edvs[jj][h];
                float4 q0 = hps4[jj][h * 4 + 0];
                float4 q1 = hps4[jj][h * 4 + 1];
                float4 q2 = hps4[jj][h * 4 + 2];
                float4 q3 = hps4[jj][h * 4 + 3];

                float p0, p1;
                {
                    float e = esr[0] + ed.z;
                    float sa = (e > 0.f) ? esA[0] : esB[0];
                    float sb = (e > 0.f) ? ed.x : ed.y;
                    p0 = (m0 & (1u << bp)) ? sa * sb : 0.f;
                }
                {
                    float e = esr[1] + ed.z;
                    float sa = (e > 0.f) ? esA[1] : esB[1];
                    float sb = (e > 0.f) ? ed.x : ed.y;
                    p1 = (m1 & (1u << bp)) ? sa * sb : 0.f;
                }
                ssum[0] += p0;  ssum[1] += p1;

                acc[0][0]  = fmaf(p0, q0.x, acc[0][0]);
                acc[0][1]  = fmaf(p0, q0.y, acc[0][1]);
                acc[0][2]  = fmaf(p0, q0.z, acc[0][2]);
                acc[0][3]  = fmaf(p0, q0.w, acc[0][3]);
                acc[0][4]  = fmaf(p0, q1.x, acc[0][4]);
                acc[0][5]  = fmaf(p0, q1.y, acc[0][5]);
                acc[0][6]  = fmaf(p0, q1.z, acc[0][6]);
                acc[0][7]  = fmaf(p0, q1.w, acc[0][7]);
                acc[0][8]  = fmaf(p0, q2.x, acc[0][8]);
                acc[0][9]  = fmaf(p0, q2.y, acc[0][9]);
                acc[0][10] = fmaf(p0, q2.z, acc[0][10]);
                acc[0][11] = fmaf(p0, q2.w, acc[0][11]);
                acc[0][12] = fmaf(p0, q3.x, acc[0][12]);
                acc[0][13] = fmaf(p0, q3.y, acc[0][13]);
                acc[0][14] = fmaf(p0, q3.z, acc[0][14]);
                acc[0][15] = fmaf(p0, q3.w, acc[0][15]);

                acc[1][0]  = fmaf(p1, q0.x, acc[1][0]);
                acc[1][1]  = fmaf(p1, q0.y, acc[1][1]);
                acc[1][2]  = fmaf(p1, q0.z, acc[1][2]);
                acc[1][3]  = fmaf(p1, q0.w, acc[1][3]);
                acc[1][4]  = fmaf(p1, q1.x, acc[1][4]);
                acc[1][5]  = fmaf(p1, q1.y, acc[1][5]);
                acc[1][6]  = fmaf(p1, q1.z, acc[1][6]);
                acc[1][7]  = fmaf(p1, q1.w, acc[1][7]);
                acc[1][8]  = fmaf(p1, q2.x, acc[1][8]);
                acc[1][9]  = fmaf(p1, q2.y, acc[1][9]);
                acc[1][10] = fmaf(p1, q2.z, acc[1][10]);
                acc[1][11] = fmaf(p1, q2.w, acc[1][11]);
                acc[1][12] = fmaf(p1, q3.x, acc[1][12]);
                acc[1][13] = fmaf(p1, q3.y, acc[1][13]);
                acc[1][14] = fmaf(p1, q3.z, acc[1][14]);
                acc[1][15] = fmaf(p1, q3.w, acc[1][15]);
            }
        }
    }

#pragma unroll
    for (int r = 0; r < 2; ++r) {
        if (irow[r] < Nn) {
            int bn = b * Nn + irow[r];
            pss[bn * 4 + h] = ssum[r];
            float4* dst = (float4*)&pacc[bn * 64 + h * 16];
            dst[0] = make_float4(acc[r][0],  acc[r][1],  acc[r][2],  acc[r][3]);
            dst[1] = make_float4(acc[r][4],  acc[r][5],  acc[r][6],  acc[r][7]);
            dst[2] = make_float4(acc[r][8],  acc[r][9],  acc[r][10], acc[r][11]);
            dst[3] = make_float4(acc[r][12], acc[r][13], acc[r][14], acc[r][15]);
        }
    }
}

// ---------------- combine j-split partials, normalize, ReLU -----------------
template <int LAYER>
__global__ __launch_bounds__(256) void gat_combine_kernel()
{
    float* __restrict__ hout = (LAYER == 0) ? d_h2 : d_h;
    int idx = blockIdx.x * 256 + threadIdx.x;      // over BN*16 float4s
    if (idx >= BN * 16) return;
    int bn = idx >> 4;
    int f4 = idx & 15;
    int h  = f4 >> 2;
    float s = d_pss0[bn * 4 + h] + d_pss1[bn * 4 + h];
    float inv = (s > 0.f) ? __fdividef(1.f, s) : 0.f;
    float4 a0 = ((const float4*)d_pacc0)[idx];
    float4 a1 = ((const float4*)d_pacc1)[idx];
    float4 v;
    v.x = fmaxf((a0.x + a1.x) * inv, 0.f);
    v.y = fmaxf((a0.y + a1.y) * inv, 0.f);
    v.z = fmaxf((a0.z + a1.z) * inv, 0.f);
    v.w = fmaxf((a0.w + a1.w) * inv, 0.f);
    ((float4*)hout)[idx] = v;
}

// ---------------- output head: (B,N,64) @ (3,64)^T -> (B,3,N) ---------------
__global__ __launch_bounds__(256) void out_kernel(
    const float* __restrict__ outW, const float* __restrict__ outb,
    float* __restrict__ out)
{
    int gw   = (blockIdx.x * blockDim.x + threadIdx.x) >> 5;
    int lane = threadIdx.x & 31;
    if (gw >= BN) return;
    float ha = d_h[gw * 64 + lane];
    float hb = d_h[gw * 64 + 32 + lane];
    int b = gw / Nn, n = gw % Nn;
#pragma unroll
    for (int o = 0; o < 3; ++o) {
        float p = fmaf(ha, outW[o * 64 + lane], hb * outW[o * 64 + 32 + lane]);
#pragma unroll
        for (int off = 16; off > 0; off >>= 1)
            p += __shfl_down_sync(0xffffffffu, p, off);
        if (lane == 0)
            out[b * 3 * Nn + o * Nn + n] = p + outb[o];
    }
}

// ---------------- launch ----------------------------------------------------
extern "C" void kernel_launch(void* const* d_in, const int* in_sizes, int n_in,
                              void* d_out, int out_size)
{
    const float* x     = (const float*)d_in[0];
    const float* adj   = (const float*)d_in[1];   // int32 payload, cast inside prep
    const float* Wih0  = (const float*)d_in[2];
    const float* Whh0  = (const float*)d_in[3];
    const float* bih0  = (const float*)d_in[4];
    const float* bhh0  = (const float*)d_in[5];
    const float* Wih1  = (const float*)d_in[6];
    const float* Whh1  = (const float*)d_in[7];
    const float* bih1  = (const float*)d_in[8];
    const float* bhh1  = (const float*)d_in[9];
    const float* g0W   = (const float*)d_in[10];
    const float* g0as  = (const float*)d_in[11];
    const float* g0ad  = (const float*)d_in[12];
    const float* g1W   = (const float*)d_in[13];
    const float* g1as  = (const float*)d_in[14];
    const float* g1ad  = (const float*)d_in[15];
    const float* outW  = (const float*)d_in[16];
    const float* outb  = (const float*)d_in[17];
    float* out = (float*)d_out;

    prep_kernel<<<(Nn * NW + 255) / 256, 256>>>(adj, Whh0, bih0, bhh0,
                                                Wih1, Whh1, bih1, bhh1, g0W, g1W);
    lstm_kernel<<<BN / SPB, 256>>>(x, Wih0);

    dim3 agrid((Nn + 63) / 64, Bb, 2);

    gat_proj_kernel<0><<<BN / 4, 256>>>(g0as, g0ad);
    gat_attn_kernel<<<agrid, 128>>>();
    gat_combine_kernel<0><<<(BN * 16 + 255) / 256, 256>>>();

    gat_proj_kernel<1><<<BN / 4, 256>>>(g1as, g1ad);
    gat_attn_kernel<<<agrid, 128>>>();
    gat_combine_kernel<1><<<(BN * 16 + 255) / 256, 256>>>();

    out_kernel<<<(BN * 32 + 255) / 256, 256>>>(outW, outb, out);
}

// round 5
// speedup vs baseline: 1.8624x; 1.1156x over previous
#include <cuda_runtime.h>

// Problem constants (fixed shapes from reference)
constexpr int Bb   = 8;
constexpr int Tt   = 12;
constexpr int Nn   = 1500;
constexpr int HID_ = 64;
constexpr int BN   = Bb * Nn;     // 12000
constexpr int SPB  = 32;          // sequences per LSTM block
constexpr int SPBP = 36;          // padded row
constexpr int NW   = 47;          // ceil(1500/32) adjacency bitmask words per row
constexpr int ZCH  = 4;           // attention j-splits
constexpr int JRANGE = 384;       // j per split (last split shorter)

#define DEVINL __device__ __forceinline__
typedef unsigned long long ull;

// ---------------- scratch (device globals; no allocation allowed) ----------
__device__ __align__(16) float d_Wp0[64 * 256];    // [j][u][gate] packed, layer0 Whh
__device__ __align__(16) float d_Wp1i[64 * 256];   // layer1 Wih packed
__device__ __align__(16) float d_Wp1h[64 * 256];   // layer1 Whh packed
__device__ float d_b0[256], d_b1[256];
__device__ __align__(16) float d_g0WT[64 * 64], d_g1WT[64 * 64];
__device__ __align__(16) float d_h [BN * 64];      // LSTM out / GAT1 out
__device__ __align__(16) float d_h2[BN * 64];      // GAT0 out
__device__ __align__(16) float d_hp[BN * 64];      // projected features (per layer)
__device__ __align__(16) float4 d_esv[BN * 4];     // (exp(es), exp(0.2es), es, 0)
__device__ __align__(16) float4 d_edv[BN * 4];     // (exp(ed), exp(0.2ed), ed, 0)
__device__ unsigned d_adjb[Nn * NW];               // bitpacked adjacency
__device__ __align__(16) float d_pacc[ZCH * BN * 64];
__device__ float d_pss[ZCH * BN * 4];

DEVINL float fsig(float z)  { return __fdividef(1.f, 1.f + __expf(-z)); }
DEVINL float ftanh(float z) { return __fdividef(2.f, 1.f + __expf(-2.f * z)) - 1.f; }

// ---- packed fp32x2 helpers -------------------------------------------------
DEVINL ull dup2(float x) {
    ull r; unsigned xi = __float_as_uint(x);
    asm("mov.b64 %0, {%1, %1};" : "=l"(r) : "r"(xi));
    return r;
}
DEVINL ull pk2(float lo, float hi) {
    ull r;
    asm("mov.b64 %0, {%1, %2};" : "=l"(r)
        : "r"(__float_as_uint(lo)), "r"(__float_as_uint(hi)));
    return r;
}
DEVINL ull ffma2(ull a, ull b, ull c) {
    ull d;
    asm("fma.rn.f32x2 %0, %1, %2, %3;" : "=l"(d) : "l"(a), "l"(b), "l"(c));
    return d;
}
DEVINL float2 unpk(ull v) {
    unsigned lo, hi;
    asm("mov.b64 {%0, %1}, %2;" : "=r"(lo), "=r"(hi) : "l"(v));
    return make_float2(__uint_as_float(lo), __uint_as_float(hi));
}

// ---------------- prep: packed transposes + fused biases + adj bitpack ------
__global__ void prep_kernel(const float* __restrict__ adj_,
                            const float* __restrict__ Whh0,
                            const float* __restrict__ bih0, const float* __restrict__ bhh0,
                            const float* __restrict__ Wih1, const float* __restrict__ Whh1,
                            const float* __restrict__ bih1, const float* __restrict__ bhh1,
                            const float* __restrict__ g0W,  const float* __restrict__ g1W)
{
    const int* __restrict__ adj = (const int*)adj_;
    int idx = blockIdx.x * blockDim.x + threadIdx.x;
    if (idx < 16384) {
        int r = idx >> 6, j = idx & 63;
        int g = r >> 6, u = r & 63;
        int p = j * 256 + u * 4 + g;
        d_Wp0 [p] = Whh0[idx];
        d_Wp1i[p] = Wih1[idx];
        d_Wp1h[p] = Whh1[idx];
    }
    if (idx < 256) {
        d_b0[idx] = bih0[idx] + bhh0[idx];
        d_b1[idx] = bih1[idx] + bhh1[idx];
    }
    if (idx < 4096) {
        int o = idx >> 6, k = idx & 63;
        d_g0WT[k * 64 + o] = g0W[idx];
        d_g1WT[k * 64 + o] = g1W[idx];
    }
    if (idx < Nn * NW) {
        int i = idx / NW, w = idx % NW;
        unsigned m = 0;
        int jb = w * 32;
#pragma unroll 8
        for (int b = 0; b < 32; ++b) {
            int j = jb + b;
            if (j < Nn && adj[i * Nn + j] > 0) m |= (1u << b);
        }
        d_adjb[idx] = m;
    }
}

// ---------------- 2-layer LSTM (fp32x2 gate GEMMs) --------------------------
__global__ __launch_bounds__(256) void lstm_kernel(
    const float* __restrict__ x, const float* __restrict__ Wih0)
{
    __shared__ __align__(16) float xs[Tt][SPB];
    __shared__ __align__(16) float h0s[HID_][SPBP];
    __shared__ __align__(16) float h1s[HID_][SPBP];

    const int tid = threadIdx.x;
    const int u   = tid & 63;
    const int sg  = tid >> 6;
    const int sbase = sg * 8;
    const int bn0 = blockIdx.x * SPB;

    for (int idx = tid; idx < Tt * SPB; idx += 256) {
        int tt = idx / SPB, s = idx % SPB;
        int bn = bn0 + s;
        int b = bn / Nn, n = bn % Nn;
        xs[tt][s] = x[(b * Tt + tt) * Nn + n];
    }
    for (int idx = tid; idx < HID_ * SPBP; idx += 256) {
        (&h0s[0][0])[idx] = 0.f;
        (&h1s[0][0])[idx] = 0.f;
    }

    float c0[8], c1[8];
#pragma unroll
    for (int s = 0; s < 8; ++s) { c0[s] = 0.f; c1[s] = 0.f; }

    // invariant packed weights / biases
    const ull wi0_i2 = dup2(Wih0[u]),       wi0_f2 = dup2(Wih0[64 + u]);
    const ull wi0_g2 = dup2(Wih0[128 + u]), wi0_o2 = dup2(Wih0[192 + u]);
    const ull b0_i2 = dup2(d_b0[u]), b0_f2 = dup2(d_b0[64 + u]);
    const ull b0_g2 = dup2(d_b0[128 + u]), b0_o2 = dup2(d_b0[192 + u]);
    const ull b1_i2 = dup2(d_b1[u]), b1_f2 = dup2(d_b1[64 + u]);
    const ull b1_g2 = dup2(d_b1[128 + u]), b1_o2 = dup2(d_b1[192 + u]);

    const float4* __restrict__ Wp0  = (const float4*)&d_Wp0 [u * 4];
    const float4* __restrict__ Wp1i = (const float4*)&d_Wp1i[u * 4];
    const float4* __restrict__ Wp1h = (const float4*)&d_Wp1h[u * 4];

    __syncthreads();

    float h1v[8];
    for (int t = 0; t < Tt; ++t) {
        ull ai2[4], af2[4], ag2[4], ao2[4];
        // ---- layer 0 init from x ----
        {
            ulonglong2 xA = *(const ulonglong2*)&xs[t][sbase];
            ulonglong2 xB = *(const ulonglong2*)&xs[t][sbase + 4];
            ull xv2[4] = {xA.x, xA.y, xB.x, xB.y};
#pragma unroll
            for (int p = 0; p < 4; ++p) {
                ai2[p] = ffma2(wi0_i2, xv2[p], b0_i2);
                af2[p] = ffma2(wi0_f2, xv2[p], b0_f2);
                ag2[p] = ffma2(wi0_g2, xv2[p], b0_g2);
                ao2[p] = ffma2(wi0_o2, xv2[p], b0_o2);
            }
        }
#pragma unroll 4
        for (int j = 0; j < HID_; ++j) {
            float4 w = Wp0[j * 64];
            ull wx = dup2(w.x), wy = dup2(w.y), wz = dup2(w.z), ww = dup2(w.w);
            ulonglong2 hA = *(const ulonglong2*)&h0s[j][sbase];
            ulonglong2 hB = *(const ulonglong2*)&h0s[j][sbase + 4];
            ull hv2[4] = {hA.x, hA.y, hB.x, hB.y};
#pragma unroll
            for (int p = 0; p < 4; ++p) {
                ai2[p] = ffma2(wx, hv2[p], ai2[p]);
                af2[p] = ffma2(wy, hv2[p], af2[p]);
                ag2[p] = ffma2(wz, hv2[p], ag2[p]);
                ao2[p] = ffma2(ww, hv2[p], ao2[p]);
            }
        }
        float h0v[8];
#pragma unroll
        for (int p = 0; p < 4; ++p) {
            float2 vi = unpk(ai2[p]), vf = unpk(af2[p]);
            float2 vg = unpk(ag2[p]), vo = unpk(ao2[p]);
            int s0 = 2 * p, s1 = 2 * p + 1;
            c0[s0] = fmaf(fsig(vf.x), c0[s0], fsig(vi.x) * ftanh(vg.x));
            h0v[s0] = fsig(vo.x) * ftanh(c0[s0]);
            c0[s1] = fmaf(fsig(vf.y), c0[s1], fsig(vi.y) * ftanh(vg.y));
            h0v[s1] = fsig(vo.y) * ftanh(c0[s1]);
        }
        __syncthreads();
#pragma unroll
        for (int s = 0; s < 8; ++s) h0s[u][sbase + s] = h0v[s];
        __syncthreads();

        // ---- layer 1 ----
#pragma unroll
        for (int p = 0; p < 4; ++p) {
            ai2[p] = b1_i2; af2[p] = b1_f2; ag2[p] = b1_g2; ao2[p] = b1_o2;
        }
#pragma unroll 4
        for (int j = 0; j < HID_; ++j) {
            float4 w = Wp1i[j * 64];
            ull wx = dup2(w.x), wy = dup2(w.y), wz = dup2(w.z), ww = dup2(w.w);
            ulonglong2 hA = *(const ulonglong2*)&h0s[j][sbase];
            ulonglong2 hB = *(const ulonglong2*)&h0s[j][sbase + 4];
            ull hv2[4] = {hA.x, hA.y, hB.x, hB.y};
#pragma unroll
            for (int p = 0; p < 4; ++p) {
                ai2[p] = ffma2(wx, hv2[p], ai2[p]);
                af2[p] = ffma2(wy, hv2[p], af2[p]);
                ag2[p] = ffma2(wz, hv2[p], ag2[p]);
                ao2[p] = ffma2(ww, hv2[p], ao2[p]);
            }
        }
#pragma unroll 4
        for (int j = 0; j < HID_; ++j) {
            float4 w = Wp1h[j * 64];
            ull wx = dup2(w.x), wy = dup2(w.y), wz = dup2(w.z), ww = dup2(w.w);
            ulonglong2 hA = *(const ulonglong2*)&h1s[j][sbase];
            ulonglong2 hB = *(const ulonglong2*)&h1s[j][sbase + 4];
            ull hv2[4] = {hA.x, hA.y, hB.x, hB.y};
#pragma unroll
            for (int p = 0; p < 4; ++p) {
                ai2[p] = ffma2(wx, hv2[p], ai2[p]);
                af2[p] = ffma2(wy, hv2[p], af2[p]);
                ag2[p] = ffma2(wz, hv2[p], ag2[p]);
                ao2[p] = ffma2(ww, hv2[p], ao2[p]);
            }
        }
#pragma unroll
        for (int p = 0; p < 4; ++p) {
            float2 vi = unpk(ai2[p]), vf = unpk(af2[p]);
            float2 vg = unpk(ag2[p]), vo = unpk(ao2[p]);
            int s0 = 2 * p, s1 = 2 * p + 1;
            c1[s0] = fmaf(fsig(vf.x), c1[s0], fsig(vi.x) * ftanh(vg.x));
            h1v[s0] = fsig(vo.x) * ftanh(c1[s0]);
            c1[s1] = fmaf(fsig(vf.y), c1[s1], fsig(vi.y) * ftanh(vg.y));
            h1v[s1] = fsig(vo.y) * ftanh(c1[s1]);
        }
        __syncthreads();
#pragma unroll
        for (int s = 0; s < 8; ++s) h1s[u][sbase + s] = h1v[s];
        __syncthreads();
    }

#pragma unroll
    for (int s = 0; s < 8; ++s)
        d_h[(bn0 + sbase + s) * 64 + u] = h1v[s];
}

// ---------------- GAT projection + factorized attention exponentials -------
template <int LAYER>
__global__ __launch_bounds__(256) void gat_proj_kernel(
    const float* __restrict__ asrc, const float* __restrict__ adst)
{
    const float* __restrict__ hin = (LAYER == 0) ? d_h : d_h2;
    const float* __restrict__ WT  = (LAYER == 0) ? d_g0WT : d_g1WT;

    const int t  = threadIdx.x;
    const int o  = t & 63;
    const int lo = t >> 6;
    const int bn = blockIdx.x * 4 + lo;

    __shared__ float hs[4][64];
    hs[lo][o] = hin[bn * 64 + o];
    __syncthreads();

    float acc = 0.f;
#pragma unroll
    for (int k = 0; k < 64; ++k)
        acc = fmaf(hs[lo][k], WT[k * 64 + o], acc);

    d_hp[bn * 64 + o] = acc;

    float vs = acc * asrc[o];
    float vd = acc * adst[o];
#pragma unroll
    for (int off = 8; off > 0; off >>= 1) {
        vs += __shfl_down_sync(0xffffffffu, vs, off, 16);
        vd += __shfl_down_sync(0xffffffffu, vd, off, 16);
    }
    if ((o & 15) == 0) {
        int hh = o >> 4;
        d_esv[bn * 4 + hh] = make_float4(__expf(vs), __expf(0.2f * vs), vs, 0.f);
        d_edv[bn * 4 + hh] = make_float4(__expf(vd), __expf(0.2f * vd), vd, 0.f);
    }
}

// ---------------- GAT attention aggregate (4-way j-split, fp32x2) -----------
// block: 128 threads = 32 rslots x 4 heads; each thread owns 2 rows
// grid: (ceil(N/64), B, ZCH)
__global__ __launch_bounds__(128) void gat_attn_kernel()
{
    constexpr int JC = 64;
    const int b  = blockIdx.y;
    const int z  = blockIdx.z;
    const int i0 = blockIdx.x * 64;
    const int t  = threadIdx.x;
    const int h  = t & 3;
    const int rs = t >> 2;

    float* __restrict__ pacc = d_pacc + z * (BN * 64);
    float* __restrict__ pss  = d_pss  + z * (BN * 4);

    __shared__ __align__(16) float4 hps4[JC][16];   // 16 KB  [jj][k4]
    __shared__ __align__(16) float4 edvs[JC][4];    // 4 KB   [jj][h]
    __shared__ unsigned adjw[64][2];                // 512 B

    ull acc2[2][8];
#pragma unroll
    for (int r = 0; r < 2; ++r)
#pragma unroll
        for (int d = 0; d < 8; ++d) acc2[r][d] = 0ull;
    float ssum[2] = {0.f, 0.f};

    int   irow[2];
    float esA[2], esB[2], esr[2];
#pragma unroll
    for (int r = 0; r < 2; ++r) {
        irow[r] = i0 + rs + 32 * r;
        float4 ev = make_float4(0.f, 0.f, 0.f, 0.f);
        if (irow[r] < Nn) ev = d_esv[(b * Nn + irow[r]) * 4 + h];
        esA[r] = ev.x; esB[r] = ev.y; esr[r] = ev.z;
    }

    const int jbeg = z * JRANGE;
    const int jend = min(jbeg + JRANGE, Nn);

    for (int j0 = jbeg; j0 < jend; j0 += JC) {
        __syncthreads();
        for (int idx = t; idx < JC * 16; idx += 128) {
            int jj = idx >> 4, k4 = idx & 15;
            int j = j0 + jj;
            float4 v = make_float4(0.f, 0.f, 0.f, 0.f);
            if (j < Nn) v = ((const float4*)d_hp)[(b * Nn + j) * 16 + k4];
            hps4[jj][k4] = v;
        }
        for (int idx = t; idx < JC * 4; idx += 128) {
            int jj = idx >> 2, hh = idx & 3;
            int j = j0 + jj;
            float4 v = make_float4(0.f, 0.f, 0.f, 0.f);
            if (j < Nn) v = d_edv[(b * Nn + j) * 4 + hh];
            edvs[jj][hh] = v;
        }
        if (t < 64) {
            int i = i0 + t;
            int w0 = j0 >> 5;
#pragma unroll
            for (int w = 0; w < 2; ++w) {
                unsigned m = 0;
                if (i < Nn && (w0 + w) < NW) m = d_adjb[i * NW + w0 + w];
                adjw[t][w] = m;
            }
        }
        __syncthreads();

#pragma unroll
        for (int w = 0; w < 2; ++w) {
            unsigned m0 = adjw[rs][w];
            unsigned m1 = adjw[rs + 32][w];
            const int jjb = w * 32;
#pragma unroll 4
            for (int bp = 0; bp < 32; ++bp) {
                const int jj = jjb + bp;
                float4 ed = edvs[jj][h];
                const ulonglong2* q = (const ulonglong2*)&hps4[jj][h * 4];
                ulonglong2 qa = q[0], qb = q[1], qc = q[2], qd = q[3];

                float p0, p1;
                {
                    float e = esr[0] + ed.z;
                    float sa = (e > 0.f) ? esA[0] : esB[0];
                    float sb = (e > 0.f) ? ed.x : ed.y;
                    p0 = (m0 & (1u << bp)) ? sa * sb : 0.f;
                }
                {
                    float e = esr[1] + ed.z;
                    float sa = (e > 0.f) ? esA[1] : esB[1];
                    float sb = (e > 0.f) ? ed.x : ed.y;
                    p1 = (m1 & (1u << bp)) ? sa * sb : 0.f;
                }
                ssum[0] += p0;  ssum[1] += p1;
                ull pp0 = dup2(p0), pp1 = dup2(p1);

                acc2[0][0] = ffma2(pp0, qa.x, acc2[0][0]);
                acc2[0][1] = ffma2(pp0, qa.y, acc2[0][1]);
                acc2[0][2] = ffma2(pp0, qb.x, acc2[0][2]);
                acc2[0][3] = ffma2(pp0, qb.y, acc2[0][3]);
                acc2[0][4] = ffma2(pp0, qc.x, acc2[0][4]);
                acc2[0][5] = ffma2(pp0, qc.y, acc2[0][5]);
                acc2[0][6] = ffma2(pp0, qd.x, acc2[0][6]);
                acc2[0][7] = ffma2(pp0, qd.y, acc2[0][7]);

                acc2[1][0] = ffma2(pp1, qa.x, acc2[1][0]);
                acc2[1][1] = ffma2(pp1, qa.y, acc2[1][1]);
                acc2[1][2] = ffma2(pp1, qb.x, acc2[1][2]);
                acc2[1][3] = ffma2(pp1, qb.y, acc2[1][3]);
                acc2[1][4] = ffma2(pp1, qc.x, acc2[1][4]);
                acc2[1][5] = ffma2(pp1, qc.y, acc2[1][5]);
                acc2[1][6] = ffma2(pp1, qd.x, acc2[1][6]);
                acc2[1][7] = ffma2(pp1, qd.y, acc2[1][7]);
            }
        }
    }

#pragma unroll
    for (int r = 0; r < 2; ++r) {
        if (irow[r] < Nn) {
            int bn = b * Nn + irow[r];
            pss[bn * 4 + h] = ssum[r];
            ulonglong2* dst = (ulonglong2*)&pacc[bn * 64 + h * 16];
#pragma unroll
            for (int k = 0; k < 4; ++k)
                dst[k] = make_ulonglong2(acc2[r][2 * k], acc2[r][2 * k + 1]);
        }
    }
}

// ---------------- combine j-split partials, normalize, ReLU -----------------
template <int LAYER>
__global__ __launch_bounds__(256) void gat_combine_kernel()
{
    float* __restrict__ hout = (LAYER == 0) ? d_h2 : d_h;
    int idx = blockIdx.x * 256 + threadIdx.x;      // over BN*16 float4s
    if (idx >= BN * 16) return;
    int bn = idx >> 4;
    int f4 = idx & 15;
    int h  = f4 >> 2;
    float s = 0.f;
#pragma unroll
    for (int z = 0; z < ZCH; ++z) s += d_pss[z * (BN * 4) + bn * 4 + h];
    float inv = (s > 0.f) ? __fdividef(1.f, s) : 0.f;
    float4 a = make_float4(0.f, 0.f, 0.f, 0.f);
#pragma unroll
    for (int z = 0; z < ZCH; ++z) {
        float4 v = ((const float4*)(d_pacc + z * (BN * 64)))[idx];
        a.x += v.x; a.y += v.y; a.z += v.z; a.w += v.w;
    }
    float4 v;
    v.x = fmaxf(a.x * inv, 0.f);
    v.y = fmaxf(a.y * inv, 0.f);
    v.z = fmaxf(a.z * inv, 0.f);
    v.w = fmaxf(a.w * inv, 0.f);
    ((float4*)hout)[idx] = v;
}

// ---------------- output head: (B,N,64) @ (3,64)^T -> (B,3,N) ---------------
__global__ __launch_bounds__(256) void out_kernel(
    const float* __restrict__ outW, const float* __restrict__ outb,
    float* __restrict__ out)
{
    int gw   = (blockIdx.x * blockDim.x + threadIdx.x) >> 5;
    int lane = threadIdx.x & 31;
    if (gw >= BN) return;
    float ha = d_h[gw * 64 + lane];
    float hb = d_h[gw * 64 + 32 + lane];
    int b = gw / Nn, n = gw % Nn;
#pragma unroll
    for (int o = 0; o < 3; ++o) {
        float p = fmaf(ha, outW[o * 64 + lane], hb * outW[o * 64 + 32 + lane]);
#pragma unroll
        for (int off = 16; off > 0; off >>= 1)
            p += __shfl_down_sync(0xffffffffu, p, off);
        if (lane == 0)
            out[b * 3 * Nn + o * Nn + n] = p + outb[o];
    }
}

// ---------------- launch ----------------------------------------------------
extern "C" void kernel_launch(void* const* d_in, const int* in_sizes, int n_in,
                              void* d_out, int out_size)
{
    const float* x     = (const float*)d_in[0];
    const float* adj   = (const float*)d_in[1];   // int32 payload, cast inside prep
    const float* Wih0  = (const float*)d_in[2];
    const float* Whh0  = (const float*)d_in[3];
    const float* bih0  = (const float*)d_in[4];
    const float* bhh0  = (const float*)d_in[5];
    const float* Wih1  = (const float*)d_in[6];
    const float* Whh1  = (const float*)d_in[7];
    const float* bih1  = (const float*)d_in[8];
    const float* bhh1  = (const float*)d_in[9];
    const float* g0W   = (const float*)d_in[10];
    const float* g0as  = (const float*)d_in[11];
    const float* g0ad  = (const float*)d_in[12];
    const float* g1W   = (const float*)d_in[13];
    const float* g1as  = (const float*)d_in[14];
    const float* g1ad  = (const float*)d_in[15];
    const float* outW  = (const float*)d_in[16];
    const float* outb  = (const float*)d_in[17];
    float* out = (float*)d_out;

    prep_kernel<<<(Nn * NW + 255) / 256, 256>>>(adj, Whh0, bih0, bhh0,
                                                Wih1, Whh1, bih1, bhh1, g0W, g1W);
    lstm_kernel<<<BN / SPB, 256>>>(x, Wih0);

    dim3 agrid((Nn + 63) / 64, Bb, ZCH);

    gat_proj_kernel<0><<<BN / 4, 256>>>(g0as, g0ad);
    gat_attn_kernel<<<agrid, 128>>>();
    gat_combine_kernel<0><<<(BN * 16 + 255) / 256, 256>>>();

    gat_proj_kernel<1><<<BN / 4, 256>>>(g1as, g1ad);
    gat_attn_kernel<<<agrid, 128>>>();
    gat_combine_kernel<1><<<(BN * 16 + 255) / 256, 256>>>();

    out_kernel<<<(BN * 32 + 255) / 256, 256>>>(outW, outb, out);
}

// round 9
// speedup vs baseline: 2.2063x; 1.1847x over previous
#include <cuda_runtime.h>

// Problem constants (fixed shapes from reference)
constexpr int Bb   = 8;
constexpr int Tt   = 12;
constexpr int Nn   = 1500;
constexpr int HID_ = 64;
constexpr int BN   = Bb * Nn;     // 12000
constexpr int SPB  = 32;          // sequences per LSTM block
constexpr int SPBP = 36;          // padded row
constexpr int NW   = 47;          // ceil(1500/32) adjacency bitmask words per row
constexpr int ZCH  = 4;           // attention j-splits
constexpr int JRANGE = 384;       // j per split (last split shorter)

#define DEVINL __device__ __forceinline__
typedef unsigned long long ull;

// ---------------- scratch (device globals; no allocation allowed) ----------
__device__ __align__(16) float d_Wp0[64 * 256];    // [j][u][gate] packed, layer0 Whh
__device__ __align__(16) float d_Wp1i[64 * 256];   // layer1 Wih packed
__device__ __align__(16) float d_Wp1h[64 * 256];   // layer1 Whh packed
__device__ float d_b0[256], d_b1[256];
__device__ __align__(16) float d_g0WT[64 * 64], d_g1WT[64 * 64];
__device__ __align__(16) float d_h [BN * 64];      // LSTM out / GAT1 out
__device__ __align__(16) float d_h2[BN * 64];      // GAT0 out
__device__ __align__(16) float d_hp[BN * 64];      // projected features (per layer)
__device__ __align__(16) float4 d_esv[BN * 4];     // (exp(es), exp(0.2es), es, 0)
__device__ __align__(16) float4 d_edv[BN * 4];     // (exp(ed), exp(0.2ed), ed, 0)
__device__ unsigned d_adjb[Nn * NW];               // bitpacked adjacency
__device__ __align__(16) float d_pacc[ZCH * BN * 64];
__device__ float d_pss[ZCH * BN * 4];

DEVINL float fsig(float z)  { return __fdividef(1.f, 1.f + __expf(-z)); }
DEVINL float ftanh(float z) { return __fdividef(2.f, 1.f + __expf(-2.f * z)) - 1.f; }

// ---- packed fp32x2 helpers -------------------------------------------------
DEVINL ull dup2(float x) {
    ull r; unsigned xi = __float_as_uint(x);
    asm("mov.b64 %0, {%1, %1};" : "=l"(r) : "r"(xi));
    return r;
}
DEVINL ull pk2(float lo, float hi) {
    ull r;
    asm("mov.b64 %0, {%1, %2};" : "=l"(r)
        : "r"(__float_as_uint(lo)), "r"(__float_as_uint(hi)));
    return r;
}
DEVINL ull ffma2(ull a, ull b, ull c) {
    ull d;
    asm("fma.rn.f32x2 %0, %1, %2, %3;" : "=l"(d) : "l"(a), "l"(b), "l"(c));
    return d;
}
DEVINL float2 unpk(ull v) {
    unsigned lo, hi;
    asm("mov.b64 {%0, %1}, %2;" : "=r"(lo), "=r"(hi) : "l"(v));
    return make_float2(__uint_as_float(lo), __uint_as_float(hi));
}

// ---------------- prep: packed transposes + fused biases + adj bitpack ------
__global__ void prep_kernel(const float* __restrict__ adj_,
                            const float* __restrict__ Whh0,
                            const float* __restrict__ bih0, const float* __restrict__ bhh0,
                            const float* __restrict__ Wih1, const float* __restrict__ Whh1,
                            const float* __restrict__ bih1, const float* __restrict__ bhh1,
                            const float* __restrict__ g0W,  const float* __restrict__ g1W)
{
    const int* __restrict__ adj = (const int*)adj_;
    int idx = blockIdx.x * blockDim.x + threadIdx.x;
    if (idx < 16384) {
        int r = idx >> 6, j = idx & 63;
        int g = r >> 6, u = r & 63;
        int p = j * 256 + u * 4 + g;
        d_Wp0 [p] = Whh0[idx];
        d_Wp1i[p] = Wih1[idx];
        d_Wp1h[p] = Whh1[idx];
    }
    if (idx < 256) {
        d_b0[idx] = bih0[idx] + bhh0[idx];
        d_b1[idx] = bih1[idx] + bhh1[idx];
    }
    if (idx < 4096) {
        int o = idx >> 6, k = idx & 63;
        d_g0WT[k * 64 + o] = g0W[idx];
        d_g1WT[k * 64 + o] = g1W[idx];
    }
    if (idx < Nn * NW) {
        int i = idx / NW, w = idx % NW;
        unsigned m = 0;
        int jb = w * 32;
#pragma unroll 8
        for (int b = 0; b < 32; ++b) {
            int j = jb + b;
            if (j < Nn && adj[i * Nn + j] > 0) m |= (1u << b);
        }
        d_adjb[idx] = m;
    }
}

// ---------------- 2-layer LSTM (fp32x2 gate GEMMs, double-buffered h) -------
__global__ __launch_bounds__(256) void lstm_kernel(
    const float* __restrict__ x, const float* __restrict__ Wih0)
{
    __shared__ __align__(16) float xs[Tt][SPB];
    __shared__ __align__(16) float h0s[2][HID_][SPBP];
    __shared__ __align__(16) float h1s[2][HID_][SPBP];

    const int tid = threadIdx.x;
    const int u   = tid & 63;
    const int sg  = tid >> 6;
    const int sbase = sg * 8;
    const int bn0 = blockIdx.x * SPB;

    for (int idx = tid; idx < Tt * SPB; idx += 256) {
        int tt = idx / SPB, s = idx % SPB;
        int bn = bn0 + s;
        int b = bn / Nn, n = bn % Nn;
        xs[tt][s] = x[(b * Tt + tt) * Nn + n];
    }
    for (int idx = tid; idx < HID_ * SPBP; idx += 256) {
        (&h0s[0][0][0])[idx] = 0.f;
        (&h1s[0][0][0])[idx] = 0.f;
    }

    float c0[8], c1[8];
#pragma unroll
    for (int s = 0; s < 8; ++s) { c0[s] = 0.f; c1[s] = 0.f; }

    const ull wi0_i2 = dup2(Wih0[u]),       wi0_f2 = dup2(Wih0[64 + u]);
    const ull wi0_g2 = dup2(Wih0[128 + u]), wi0_o2 = dup2(Wih0[192 + u]);
    const ull b0_i2 = dup2(d_b0[u]), b0_f2 = dup2(d_b0[64 + u]);
    const ull b0_g2 = dup2(d_b0[128 + u]), b0_o2 = dup2(d_b0[192 + u]);
    const ull b1_i2 = dup2(d_b1[u]), b1_f2 = dup2(d_b1[64 + u]);
    const ull b1_g2 = dup2(d_b1[128 + u]), b1_o2 = dup2(d_b1[192 + u]);

    const float4* __restrict__ Wp0  = (const float4*)&d_Wp0 [u * 4];
    const float4* __restrict__ Wp1i = (const float4*)&d_Wp1i[u * 4];
    const float4* __restrict__ Wp1h = (const float4*)&d_Wp1h[u * 4];

    __syncthreads();

    float h1v[8];
    for (int t = 0; t < Tt; ++t) {
        const int cur = t & 1, nxt = cur ^ 1;
        ull ai2[4], af2[4], ag2[4], ao2[4];
        // ---- layer 0 init from x ----
        {
            ulonglong2 xA = *(const ulonglong2*)&xs[t][sbase];
            ulonglong2 xB = *(const ulonglong2*)&xs[t][sbase + 4];
            ull xv2[4] = {xA.x, xA.y, xB.x, xB.y};
#pragma unroll
            for (int p = 0; p < 4; ++p) {
                ai2[p] = ffma2(wi0_i2, xv2[p], b0_i2);
                af2[p] = ffma2(wi0_f2, xv2[p], b0_f2);
                ag2[p] = ffma2(wi0_g2, xv2[p], b0_g2);
                ao2[p] = ffma2(wi0_o2, xv2[p], b0_o2);
            }
        }
#pragma unroll 4
        for (int j = 0; j < HID_; ++j) {
            float4 w = Wp0[j * 64];
            ull wx = dup2(w.x), wy = dup2(w.y), wz = dup2(w.z), ww = dup2(w.w);
            ulonglong2 hA = *(const ulonglong2*)&h0s[cur][j][sbase];
            ulonglong2 hB = *(const ulonglong2*)&h0s[cur][j][sbase + 4];
            ull hv2[4] = {hA.x, hA.y, hB.x, hB.y};
#pragma unroll
            for (int p = 0; p < 4; ++p) {
                ai2[p] = ffma2(wx, hv2[p], ai2[p]);
                af2[p] = ffma2(wy, hv2[p], af2[p]);
                ag2[p] = ffma2(wz, hv2[p], ag2[p]);
                ao2[p] = ffma2(ww, hv2[p], ao2[p]);
            }
        }
        float h0v[8];
#pragma unroll
        for (int p = 0; p < 4; ++p) {
            float2 vi = unpk(ai2[p]), vf = unpk(af2[p]);
            float2 vg = unpk(ag2[p]), vo = unpk(ao2[p]);
            int s0 = 2 * p, s1 = 2 * p + 1;
            c0[s0] = fmaf(fsig(vf.x), c0[s0], fsig(vi.x) * ftanh(vg.x));
            h0v[s0] = fsig(vo.x) * ftanh(c0[s0]);
            c0[s1] = fmaf(fsig(vf.y), c0[s1], fsig(vi.y) * ftanh(vg.y));
            h0v[s1] = fsig(vo.y) * ftanh(c0[s1]);
        }
        // write into NEXT buffer: readers of cur are unaffected
#pragma unroll
        for (int s = 0; s < 8; ++s) h0s[nxt][u][sbase + s] = h0v[s];
        __syncthreads();          // h0s(t) visible in nxt

        // ---- layer 1 ----
#pragma unroll
        for (int p = 0; p < 4; ++p) {
            ai2[p] = b1_i2; af2[p] = b1_f2; ag2[p] = b1_g2; ao2[p] = b1_o2;
        }
#pragma unroll 4
        for (int j = 0; j < HID_; ++j) {
            float4 w = Wp1i[j * 64];
            ull wx = dup2(w.x), wy = dup2(w.y), wz = dup2(w.z), ww = dup2(w.w);
            ulonglong2 hA = *(const ulonglong2*)&h0s[nxt][j][sbase];
            ulonglong2 hB = *(const ulonglong2*)&h0s[nxt][j][sbase + 4];
            ull hv2[4] = {hA.x, hA.y, hB.x, hB.y};
#pragma unroll
            for (int p = 0; p < 4; ++p) {
                ai2[p] = ffma2(wx, hv2[p], ai2[p]);
                af2[p] = ffma2(wy, hv2[p], af2[p]);
                ag2[p] = ffma2(wz, hv2[p], ag2[p]);
                ao2[p] = ffma2(ww, hv2[p], ao2[p]);
            }
        }
#pragma unroll 4
        for (int j = 0; j < HID_; ++j) {
            float4 w = Wp1h[j * 64];
            ull wx = dup2(w.x), wy = dup2(w.y), wz = dup2(w.z), ww = dup2(w.w);
            ulonglong2 hA = *(const ulonglong2*)&h1s[cur][j][sbase];
            ulonglong2 hB = *(const ulonglong2*)&h1s[cur][j][sbase + 4];
            ull hv2[4] = {hA.x, hA.y, hB.x, hB.y};
#pragma unroll
            for (int p = 0; p < 4; ++p) {
                ai2[p] = ffma2(wx, hv2[p], ai2[p]);
                af2[p] = ffma2(wy, hv2[p], af2[p]);
                ag2[p] = ffma2(wz, hv2[p], ag2[p]);
                ao2[p] = ffma2(ww, hv2[p], ao2[p]);
            }
        }
#pragma unroll
        for (int p = 0; p < 4; ++p) {
            float2 vi = unpk(ai2[p]), vf = unpk(af2[p]);
            float2 vg = unpk(ag2[p]), vo = unpk(ao2[p]);
            int s0 = 2 * p, s1 = 2 * p + 1;
            c1[s0] = fmaf(fsig(vf.x), c1[s0], fsig(vi.x) * ftanh(vg.x));
            h1v[s0] = fsig(vo.x) * ftanh(c1[s0]);
            c1[s1] = fmaf(fsig(vf.y), c1[s1], fsig(vi.y) * ftanh(vg.y));
            h1v[s1] = fsig(vo.y) * ftanh(c1[s1]);
        }
#pragma unroll
        for (int s = 0; s < 8; ++s) h1s[nxt][u][sbase + s] = h1v[s];
        __syncthreads();          // h1s(t) visible; also guards next-iter overwrite
    }

#pragma unroll
    for (int s = 0; s < 8; ++s)
        d_h[(bn0 + sbase + s) * 64 + u] = h1v[s];
}

// ---------------- GAT projection + factorized attention exponentials -------
template <int LAYER>
__global__ __launch_bounds__(256) void gat_proj_kernel(
    const float* __restrict__ asrc, const float* __restrict__ adst)
{
    const float* __restrict__ hin = (LAYER == 0) ? d_h : d_h2;
    const float* __restrict__ WT  = (LAYER == 0) ? d_g0WT : d_g1WT;

    const int t  = threadIdx.x;
    const int o  = t & 63;
    const int lo = t >> 6;
    const int bn = blockIdx.x * 4 + lo;

    __shared__ float hs[4][64];
    hs[lo][o] = hin[bn * 64 + o];
    __syncthreads();

    float acc = 0.f;
#pragma unroll
    for (int k = 0; k < 64; ++k)
        acc = fmaf(hs[lo][k], WT[k * 64 + o], acc);

    d_hp[bn * 64 + o] = acc;

    float vs = acc * asrc[o];
    float vd = acc * adst[o];
#pragma unroll
    for (int off = 8; off > 0; off >>= 1) {
        vs += __shfl_down_sync(0xffffffffu, vs, off, 16);
        vd += __shfl_down_sync(0xffffffffu, vd, off, 16);
    }
    if ((o & 15) == 0) {
        int hh = o >> 4;
        d_esv[bn * 4 + hh] = make_float4(__expf(vs), __expf(0.2f * vs), vs, 0.f);
        d_edv[bn * 4 + hh] = make_float4(__expf(vd), __expf(0.2f * vd), vd, 0.f);
    }
}

// ---------------- GAT attention aggregate (4-way j-split, fp32x2) -----------
// block: 128 threads = 32 rslots x 4 heads; each thread owns 2 rows
// grid: (ceil(N/64), B, ZCH)
// hps layout [jj][head][5 float4] (pad 1) -> per-head stride 80B: the four
// lane-distinct addresses of each LDS.128 land in banks {0-3,20-23,8-11,28-31}
// -> conflict-free (the old [jj][16] layout had h0/h2 and h1/h3 collisions).
__global__ __launch_bounds__(128) void gat_attn_kernel()
{
    constexpr int JC = 64;
    const int b  = blockIdx.y;
    const int z  = blockIdx.z;
    const int i0 = blockIdx.x * 64;
    const int t  = threadIdx.x;
    const int h  = t & 3;
    const int rs = t >> 2;

    float* __restrict__ pacc = d_pacc + z * (BN * 64);
    float* __restrict__ pss  = d_pss  + z * (BN * 4);

    __shared__ __align__(16) float4 hps4[JC][4][5];  // 20 KB, padded per head
    __shared__ __align__(16) float4 edvs[JC][4];     // 4 KB
    __shared__ unsigned adjw[64][2];                 // 512 B

    ull acc2[2][8];
#pragma unroll
    for (int r = 0; r < 2; ++r)
#pragma unroll
        for (int d = 0; d < 8; ++d) acc2[r][d] = 0ull;
    ull ssum2 = 0ull;                                 // packed (row0, row1) sums
    const ull one2 = dup2(1.f);

    int   irow[2];
    float esA[2], esB[2], esr[2];
#pragma unroll
    for (int r = 0; r < 2; ++r) {
        irow[r] = i0 + rs + 32 * r;
        float4 ev = make_float4(0.f, 0.f, 0.f, 0.f);
        if (irow[r] < Nn) ev = d_esv[(b * Nn + irow[r]) * 4 + h];
        esA[r] = ev.x; esB[r] = ev.y; esr[r] = ev.z;
    }

    const int jbeg = z * JRANGE;
    const int jend = min(jbeg + JRANGE, Nn);

    for (int j0 = jbeg; j0 < jend; j0 += JC) {
        __syncthreads();
        for (int idx = t; idx < JC * 16; idx += 128) {
            int jj = idx >> 4, k4 = idx & 15;
            int j = j0 + jj;
            float4 v = make_float4(0.f, 0.f, 0.f, 0.f);
            if (j < Nn) v = ((const float4*)d_hp)[(b * Nn + j) * 16 + k4];
            hps4[jj][k4 >> 2][k4 & 3] = v;
        }
        for (int idx = t; idx < JC * 4; idx += 128) {
            int jj = idx >> 2, hh = idx & 3;
            int j = j0 + jj;
            float4 v = make_float4(0.f, 0.f, 0.f, 0.f);
            if (j < Nn) v = d_edv[(b * Nn + j) * 4 + hh];
            edvs[jj][hh] = v;
        }
        if (t < 64) {
            int i = i0 + t;
            int w0 = j0 >> 5;
#pragma unroll
            for (int w = 0; w < 2; ++w) {
                unsigned m = 0;
                if (i < Nn && (w0 + w) < NW) m = d_adjb[i * NW + w0 + w];
                adjw[t][w] = m;
            }
        }
        __syncthreads();

#pragma unroll
        for (int w = 0; w < 2; ++w) {
            unsigned m0 = adjw[rs][w];
            unsigned m1 = adjw[rs + 32][w];
            const int jjb = w * 32;
#pragma unroll 4
            for (int bp = 0; bp < 32; ++bp) {
                const int jj = jjb + bp;
                float4 ed = edvs[jj][h];
                const ulonglong2* q = (const ulonglong2*)&hps4[jj][h][0];
                ulonglong2 qa = q[0], qb = q[1];
                ull qc = *(const ull*)&hps4[jj][h][4]; // unused pad slot guard
                (void)qc;
                ulonglong2 qv2 = *(const ulonglong2*)&hps4[jj][h][2];

                float p0, p1;
                {
                    float e = esr[0] + ed.z;
                    float sa = (e > 0.f) ? esA[0] : esB[0];
                    float sb = (e > 0.f) ? ed.x : ed.y;
                    p0 = (m0 & (1u << bp)) ? sa * sb : 0.f;
                }
                {
                    float e = esr[1] + ed.z;
                    float sa = (e > 0.f) ? esA[1] : esB[1];
                    float sb = (e > 0.f) ? ed.x : ed.y;
                    p1 = (m1 & (1u << bp)) ? sa * sb : 0.f;
                }
                ssum2 = ffma2(pk2(p0, p1), one2, ssum2);
                ull pp0 = dup2(p0), pp1 = dup2(p1);

                acc2[0][0] = ffma2(pp0, qa.x,  acc2[0][0]);
                acc2[0][1] = ffma2(pp0, qa.y,  acc2[0][1]);
                acc2[0][2] = ffma2(pp0, qb.x,  acc2[0][2]);
                acc2[0][3] = ffma2(pp0, qb.y,  acc2[0][3]);
                acc2[0][4] = ffma2(pp0, qv2.x, acc2[0][4]);
                acc2[0][5] = ffma2(pp0, qv2.y, acc2[0][5]);

                acc2[1][0] = ffma2(pp1, qa.x,  acc2[1][0]);
                acc2[1][1] = ffma2(pp1, qa.y,  acc2[1][1]);
                acc2[1][2] = ffma2(pp1, qb.x,  acc2[1][2]);
                acc2[1][3] = ffma2(pp1, qb.y,  acc2[1][3]);
                acc2[1][4] = ffma2(pp1, qv2.x, acc2[1][4]);
                acc2[1][5] = ffma2(pp1, qv2.y, acc2[1][5]);

                ulonglong2 qd = *(const ulonglong2*)&hps4[jj][h][3];
                acc2[0][6] = ffma2(pp0, qd.x, acc2[0][6]);
                acc2[0][7] = ffma2(pp0, qd.y, acc2[0][7]);
                acc2[1][6] = ffma2(pp1, qd.x, acc2[1][6]);
                acc2[1][7] = ffma2(pp1, qd.y, acc2[1][7]);
            }
        }
    }

    float2 ss = unpk(ssum2);
    float ssum[2] = {ss.x, ss.y};
#pragma unroll
    for (int r = 0; r < 2; ++r) {
        if (irow[r] < Nn) {
            int bn = b * Nn + irow[r];
            pss[bn * 4 + h] = ssum[r];
            ulonglong2* dst = (ulonglong2*)&pacc[bn * 64 + h * 16];
#pragma unroll
            for (int k = 0; k < 4; ++k)
                dst[k] = make_ulonglong2(acc2[r][2 * k], acc2[r][2 * k + 1]);
        }
    }
}

// ---------------- combine j-split partials, normalize, ReLU -----------------
template <int LAYER>
__global__ __launch_bounds__(256) void gat_combine_kernel()
{
    float* __restrict__ hout = (LAYER == 0) ? d_h2 : d_h;
    int idx = blockIdx.x * 256 + threadIdx.x;      // over BN*16 float4s
    if (idx >= BN * 16) return;
    int bn = idx >> 4;
    int f4 = idx & 15;
    int h  = f4 >> 2;
    float s = 0.f;
#pragma unroll
    for (int z = 0; z < ZCH; ++z) s += d_pss[z * (BN * 4) + bn * 4 + h];
    float inv = (s > 0.f) ? __fdividef(1.f, s) : 0.f;
    float4 a = make_float4(0.f, 0.f, 0.f, 0.f);
#pragma unroll
    for (int z = 0; z < ZCH; ++z) {
        float4 v = ((const float4*)(d_pacc + z * (BN * 64)))[idx];
        a.x += v.x; a.y += v.y; a.z += v.z; a.w += v.w;
    }
    float4 v;
    v.x = fmaxf(a.x * inv, 0.f);
    v.y = fmaxf(a.y * inv, 0.f);
    v.z = fmaxf(a.z * inv, 0.f);
    v.w = fmaxf(a.w * inv, 0.f);
    ((float4*)hout)[idx] = v;
}

// ---------------- output head: (B,N,64) @ (3,64)^T -> (B,3,N) ---------------
__global__ __launch_bounds__(256) void out_kernel(
    const float* __restrict__ outW, const float* __restrict__ outb,
    float* __restrict__ out)
{
    int gw   = (blockIdx.x * blockDim.x + threadIdx.x) >> 5;
    int lane = threadIdx.x & 31;
    if (gw >= BN) return;
    float ha = d_h[gw * 64 + lane];
    float hb = d_h[gw * 64 + 32 + lane];
    int b = gw / Nn, n = gw % Nn;
#pragma unroll
    for (int o = 0; o < 3; ++o) {
        float p = fmaf(ha, outW[o * 64 + lane], hb * outW[o * 64 + 32 + lane]);
#pragma unroll
        for (int off = 16; off > 0; off >>= 1)
            p += __shfl_down_sync(0xffffffffu, p, off);
        if (lane == 0)
            out[b * 3 * Nn + o * Nn + n] = p + outb[o];
    }
}

// ---------------- launch ----------------------------------------------------
extern "C" void kernel_launch(void* const* d_in, const int* in_sizes, int n_in,
                              void* d_out, int out_size)
{
    const float* x     = (const float*)d_in[0];
    const float* adj   = (const float*)d_in[1];   // int32 payload, cast inside prep
    const float* Wih0  = (const float*)d_in[2];
    const float* Whh0  = (const float*)d_in[3];
    const float* bih0  = (const float*)d_in[4];
    const float* bhh0  = (const float*)d_in[5];
    const float* Wih1  = (const float*)d_in[6];
    const float* Whh1  = (const float*)d_in[7];
    const float* bih1  = (const float*)d_in[8];
    const float* bhh1  = (const float*)d_in[9];
    const float* g0W   = (const float*)d_in[10];
    const float* g0as  = (const float*)d_in[11];
    const float* g0ad  = (const float*)d_in[12];
    const float* g1W   = (const float*)d_in[13];
    const float* g1as  = (const float*)d_in[14];
    const float* g1ad  = (const float*)d_in[15];
    const float* outW  = (const float*)d_in[16];
    const float* outb  = (const float*)d_in[17];
    float* out = (float*)d_out;

    prep_kernel<<<(Nn * NW + 255) / 256, 256>>>(adj, Whh0, bih0, bhh0,
                                                Wih1, Whh1, bih1, bhh1, g0W, g1W);
    lstm_kernel<<<BN / SPB, 256>>>(x, Wih0);

    dim3 agrid((Nn + 63) / 64, Bb, ZCH);

    gat_proj_kernel<0><<<BN / 4, 256>>>(g0as, g0ad);
    gat_attn_kernel<<<agrid, 128>>>();
    gat_combine_kernel<0><<<(BN * 16 + 255) / 256, 256>>>();

    gat_proj_kernel<1><<<BN / 4, 256>>>(g1as, g1ad);
    gat_attn_kernel<<<agrid, 128>>>();
    gat_combine_kernel<1><<<(BN * 16 + 255) / 256, 256>>>();

    out_kernel<<<(BN * 32 + 255) / 256, 256>>>(outW, outb, out);
}